// round 2
// baseline (speedup 1.0000x reference)
#include <cuda_runtime.h>
#include <cuda_bf16.h>
#include <math.h>

// Problem constants (shapes are fixed by the dataset)
#define MAXN 50000
#define HID 128
#define NG 64
#define NC 10

// ---------------- static device scratch (no runtime allocation) ----------------
__device__ float g_dinv[MAXN];          // degree -> rsqrt(deg)
__device__ float g_h  [(size_t)MAXN * HID];   // x @ W
__device__ float g_agg[(size_t)MAXN * HID];   // scattered messages
__device__ float g_a  [(size_t)MAXN * HID];   // relu output / next-layer input
__device__ float g_pool[NG * HID];
__device__ float g_cnt[NG];

// ---------------- degree ----------------
__global__ void deg_kernel(const int* __restrict__ dst, float* __restrict__ deg, int E) {
    int i = blockIdx.x * blockDim.x + threadIdx.x;
    if (i < E) atomicAdd(&deg[dst[i]], 1.0f);
}

__global__ void dinv_kernel(float* __restrict__ dinv, int N) {
    int i = blockIdx.x * blockDim.x + threadIdx.x;
    if (i < N) dinv[i] = rsqrtf(dinv[i] + 1.0f);   // +1 self loop; deg>0 always
}

// ---------------- SGEMM: C[M,128] = A[M,128] @ B[128,128] ----------------
// Block tile 128x128, K-chunk 16, 256 threads, 8x8 register tile.
__global__ __launch_bounds__(256, 2) void sgemm128(
    const float* __restrict__ A, const float* __restrict__ B,
    float* __restrict__ C, int M)
{
    __shared__ float As[16][132];   // [k][m], padded
    __shared__ float Bs[16][128];   // [k][n]

    const int tid = threadIdx.x;
    const int tx = tid & 15;        // 0..15  (n direction)
    const int ty = tid >> 4;        // 0..15  (m direction)
    const int rowBase = blockIdx.x * 128;

    float acc[8][8];
    #pragma unroll
    for (int i = 0; i < 8; i++)
        #pragma unroll
        for (int j = 0; j < 8; j++) acc[i][j] = 0.f;

    for (int k0 = 0; k0 < 128; k0 += 16) {
        // load A tile 128x16 (transposed into As[k][m])
        #pragma unroll
        for (int l = 0; l < 2; l++) {
            int la = tid + l * 256;           // 0..511
            int ar = la >> 2;                 // 0..127 row
            int ac = (la & 3) * 4;            // 0,4,8,12
            int grow = rowBase + ar;
            float4 v = make_float4(0.f, 0.f, 0.f, 0.f);
            if (grow < M)
                v = *reinterpret_cast<const float4*>(A + (size_t)grow * 128 + k0 + ac);
            As[ac + 0][ar] = v.x; As[ac + 1][ar] = v.y;
            As[ac + 2][ar] = v.z; As[ac + 3][ar] = v.w;
        }
        // load B tile 16x128
        #pragma unroll
        for (int l = 0; l < 2; l++) {
            int lb = tid + l * 256;           // 0..511
            int br = lb >> 5;                 // 0..15
            int bc = (lb & 31) * 4;           // 0..124
            *reinterpret_cast<float4*>(&Bs[br][bc]) =
                *reinterpret_cast<const float4*>(B + (size_t)(k0 + br) * 128 + bc);
        }
        __syncthreads();

        #pragma unroll
        for (int k = 0; k < 16; k++) {
            float ra[8], rb[8];
            #pragma unroll
            for (int i = 0; i < 8; i++) ra[i] = As[k][ty * 8 + i];
            #pragma unroll
            for (int j = 0; j < 8; j++) rb[j] = Bs[k][tx * 8 + j];
            #pragma unroll
            for (int i = 0; i < 8; i++)
                #pragma unroll
                for (int j = 0; j < 8; j++) acc[i][j] += ra[i] * rb[j];
        }
        __syncthreads();
    }

    #pragma unroll
    for (int i = 0; i < 8; i++) {
        int grow = rowBase + ty * 8 + i;
        if (grow >= M) break;
        #pragma unroll
        for (int j = 0; j < 8; j += 4) {
            float4 v = make_float4(acc[i][j], acc[i][j+1], acc[i][j+2], acc[i][j+3]);
            *reinterpret_cast<float4*>(C + (size_t)grow * 128 + tx * 8 + j) = v;
        }
    }
}

// ---------------- edge scatter: agg[dst] += h[src] * (dinv[src]*dinv[dst]) ----------------
// One warp per edge; lane handles 4 consecutive floats (float4 gather + vector RED).
__global__ void scatter_kernel(
    const float* __restrict__ h, const int* __restrict__ src, const int* __restrict__ dst,
    const float* __restrict__ dinv, float* __restrict__ out, int E)
{
    int e = (blockIdx.x * blockDim.x + threadIdx.x) >> 5;
    if (e >= E) return;
    int lane = threadIdx.x & 31;

    int s = __ldg(src + e);
    int d = __ldg(dst + e);
    float norm = __ldg(dinv + s) * __ldg(dinv + d);

    float4 v = *(reinterpret_cast<const float4*>(h + (size_t)s * 128) + lane);
    v.x *= norm; v.y *= norm; v.z *= norm; v.w *= norm;

    float* op = out + (size_t)d * 128 + lane * 4;
    asm volatile("red.global.add.v4.f32 [%0], {%1, %2, %3, %4};"
                 :: "l"(op), "f"(v.x), "f"(v.y), "f"(v.z), "f"(v.w) : "memory");
}

// ---------------- self-loop + bias + relu: a = relu(agg + h*dinv^2 + b) ----------------
__global__ void fuse_relu_kernel(
    float* __restrict__ aout, const float* __restrict__ agg, const float* __restrict__ h,
    const float* __restrict__ dinv, const float* __restrict__ bias, int N)
{
    int idx = blockIdx.x * blockDim.x + threadIdx.x;   // over N*32 float4s
    if (idx >= N * 32) return;
    int row = idx >> 5;
    int q = idx & 31;
    float di = dinv[row];
    float sl = di * di;
    float4 hv = reinterpret_cast<const float4*>(h)[idx];
    float4 av = reinterpret_cast<const float4*>(agg)[idx];
    float4 bv = reinterpret_cast<const float4*>(bias)[q];
    float4 r;
    r.x = fmaxf(fmaf(hv.x, sl, av.x) + bv.x, 0.f);
    r.y = fmaxf(fmaf(hv.y, sl, av.y) + bv.y, 0.f);
    r.z = fmaxf(fmaf(hv.z, sl, av.z) + bv.z, 0.f);
    r.w = fmaxf(fmaf(hv.w, sl, av.w) + bv.w, 0.f);
    reinterpret_cast<float4*>(aout)[idx] = r;
}

// ---------------- pooling over sorted batch ids ----------------
#define POOL_ROWS 512
__global__ void pool_kernel(
    const float* __restrict__ a, const int* __restrict__ batch,
    float* __restrict__ g, float* __restrict__ cnt, int N)
{
    int c = threadIdx.x;                         // feature 0..127
    int row0 = blockIdx.x * POOL_ROWS;
    if (row0 >= N) return;
    int row1 = min(row0 + POOL_ROWS, N);

    int cur = __ldg(batch + row0);
    float acc = 0.f, count = 0.f;
    for (int r = row0; r < row1; r++) {
        int b = __ldg(batch + r);
        if (b != cur) {
            atomicAdd(&g[cur * HID + c], acc);
            if (c == 0) atomicAdd(&cnt[cur], count);
            acc = 0.f; count = 0.f; cur = b;
        }
        acc += a[(size_t)r * HID + c];
        count += 1.f;
    }
    atomicAdd(&g[cur * HID + c], acc);
    if (c == 0) atomicAdd(&cnt[cur], count);
}

// ---------------- final MLP: out = relu(g/cnt @ Wc1 + bc1) @ Wc2 + bc2 ----------------
__global__ void mlp_kernel(
    const float* __restrict__ g, const float* __restrict__ cnt,
    const float* __restrict__ Wc1, const float* __restrict__ bc1,
    const float* __restrict__ Wc2, const float* __restrict__ bc2,
    float* __restrict__ out)
{
    __shared__ float gr[HID], z[HID];
    int b = blockIdx.x;
    int t = threadIdx.x;
    float c = cnt[b];
    c = (c < 1.f) ? 1.f : c;
    gr[t] = g[b * HID + t] / c;
    __syncthreads();

    float acc = bc1[t];
    for (int k = 0; k < HID; k++) acc += gr[k] * Wc1[k * HID + t];
    z[t] = fmaxf(acc, 0.f);
    __syncthreads();

    if (t < NC) {
        float o = bc2[t];
        for (int k = 0; k < HID; k++) o += z[k] * Wc2[k * NC + t];
        out[b * NC + t] = o;
    }
}

// ---------------- launch ----------------
extern "C" void kernel_launch(void* const* d_in, const int* in_sizes, int n_in,
                              void* d_out, int out_size)
{
    const float* x    = (const float*)d_in[0];
    const int*   edge = (const int*)  d_in[1];
    const int*   batc = (const int*)  d_in[2];
    const float* W1   = (const float*)d_in[3];
    const float* b1   = (const float*)d_in[4];
    const float* W2   = (const float*)d_in[5];
    const float* b2   = (const float*)d_in[6];
    const float* Wc1  = (const float*)d_in[7];
    const float* bc1  = (const float*)d_in[8];
    const float* Wc2  = (const float*)d_in[9];
    const float* bc2  = (const float*)d_in[10];

    const int N = in_sizes[0] / HID;
    const int E = in_sizes[1] / 2;
    const int* src = edge;
    const int* dst = edge + E;

    float *dinv_p, *h_p, *agg_p, *a_p, *g_p, *cnt_p;
    cudaGetSymbolAddress((void**)&dinv_p, g_dinv);
    cudaGetSymbolAddress((void**)&h_p,   g_h);
    cudaGetSymbolAddress((void**)&agg_p, g_agg);
    cudaGetSymbolAddress((void**)&a_p,   g_a);
    cudaGetSymbolAddress((void**)&g_p,   g_pool);
    cudaGetSymbolAddress((void**)&cnt_p, g_cnt);

    const size_t featBytes = (size_t)N * HID * sizeof(float);

    // normalization
    cudaMemsetAsync(dinv_p, 0, N * sizeof(float));
    deg_kernel <<<(E + 255) / 256, 256>>>(dst, dinv_p, E);
    dinv_kernel<<<(N + 255) / 256, 256>>>(dinv_p, N);

    // layer 1
    sgemm128<<<(N + 127) / 128, 256>>>(x, W1, h_p, N);
    cudaMemsetAsync(agg_p, 0, featBytes);
    scatter_kernel<<<(E + 7) / 8, 256>>>(h_p, src, dst, dinv_p, agg_p, E);
    fuse_relu_kernel<<<(N * 32 + 255) / 256, 256>>>(a_p, agg_p, h_p, dinv_p, b1, N);

    // layer 2
    sgemm128<<<(N + 127) / 128, 256>>>(a_p, W2, h_p, N);
    cudaMemsetAsync(agg_p, 0, featBytes);
    scatter_kernel<<<(E + 7) / 8, 256>>>(h_p, src, dst, dinv_p, agg_p, E);
    fuse_relu_kernel<<<(N * 32 + 255) / 256, 256>>>(a_p, agg_p, h_p, dinv_p, b2, N);

    // pooling + MLP
    cudaMemsetAsync(g_p, 0, NG * HID * sizeof(float));
    cudaMemsetAsync(cnt_p, 0, NG * sizeof(float));
    pool_kernel<<<(N + POOL_ROWS - 1) / POOL_ROWS, HID>>>(a_p, batc, g_p, cnt_p, N);
    mlp_kernel<<<NG, HID>>>(g_p, cnt_p, Wc1, bc1, Wc2, bc2, (float*)d_out);
}

// round 3
// speedup vs baseline: 2.3856x; 2.3856x over previous
#include <cuda_runtime.h>
#include <cuda_bf16.h>
#include <math.h>

#define MAXN 50000
#define MAXE 1700000
#define HID 128
#define NG 64
#define NC 10

// ---------------- static device scratch ----------------
__device__ int   g_degi[MAXN];
__device__ int   g_rowptr[MAXN + 1];
__device__ int   g_cursor[MAXN];
__device__ int   g_csr[MAXE];
__device__ float g_dinv[MAXN];
__device__ float g_h  [(size_t)MAXN * HID];   // (x @ W) * dinv[row]
__device__ float g_a  [(size_t)MAXN * HID];   // layer activation
__device__ float g_pool[NG * HID];
__device__ float g_cnt[NG];

// ---------------- degree histogram ----------------
__global__ void hist_kernel(const int* __restrict__ dst, int* __restrict__ deg, int E) {
    int i = blockIdx.x * blockDim.x + threadIdx.x;
    if (i < E) atomicAdd(&deg[dst[i]], 1);
}

// ---------------- single-block exclusive scan of degrees -> rowptr ----------------
__global__ __launch_bounds__(1024) void scan_kernel(
    const int* __restrict__ deg, int* __restrict__ rowptr, int N)
{
    const int T = 1024;
    int t = threadIdx.x;
    int C = (N + T - 1) / T;
    int lo = t * C;
    int hi = min(lo + C, N);
    if (lo > N) lo = N;
    if (hi < lo) hi = lo;

    int s = 0;
    for (int i = lo; i < hi; i++) s += deg[i];

    // exclusive block scan of per-thread sums
    int lane = t & 31, wid = t >> 5;
    int v = s;
    #pragma unroll
    for (int o = 1; o < 32; o <<= 1) {
        int u = __shfl_up_sync(0xffffffffu, v, o);
        if (lane >= o) v += u;
    }
    __shared__ int wsum[32];
    if (lane == 31) wsum[wid] = v;
    __syncthreads();
    if (wid == 0) {
        int w = wsum[lane];
        #pragma unroll
        for (int o = 1; o < 32; o <<= 1) {
            int u = __shfl_up_sync(0xffffffffu, w, o);
            if (lane >= o) w += u;
        }
        wsum[lane] = w;
    }
    __syncthreads();
    int excl = v - s + (wid > 0 ? wsum[wid - 1] : 0);

    int run = excl;
    for (int i = lo; i < hi; i++) { rowptr[i] = run; run += deg[i]; }
    if (hi == N) rowptr[N] = run;   // every thread that reaches N writes the same total
}

// ---------------- CSR fill (cursor pre-initialized to rowptr) ----------------
__global__ void fill_kernel(const int* __restrict__ src, const int* __restrict__ dst,
                            int* __restrict__ cursor, int* __restrict__ csr, int E)
{
    int i = blockIdx.x * blockDim.x + threadIdx.x;
    if (i < E) {
        int d = dst[i];
        int p = atomicAdd(&cursor[d], 1);
        csr[p] = src[i];
    }
}

__global__ void dinv_kernel(const int* __restrict__ deg, float* __restrict__ dinv, int N) {
    int i = blockIdx.x * blockDim.x + threadIdx.x;
    if (i < N) dinv[i] = rsqrtf((float)deg[i] + 1.0f);   // +1 self loop
}

// ---------------- SGEMM: C[M,128] = (A[M,128] @ B[128,128]) * dinv[row] ----------------
__global__ __launch_bounds__(256, 2) void sgemm128(
    const float* __restrict__ A, const float* __restrict__ B,
    const float* __restrict__ dinv, float* __restrict__ C, int M)
{
    __shared__ float As[16][132];
    __shared__ float Bs[16][128];

    const int tid = threadIdx.x;
    const int tx = tid & 15;
    const int ty = tid >> 4;
    const int rowBase = blockIdx.x * 128;

    float acc[8][8];
    #pragma unroll
    for (int i = 0; i < 8; i++)
        #pragma unroll
        for (int j = 0; j < 8; j++) acc[i][j] = 0.f;

    for (int k0 = 0; k0 < 128; k0 += 16) {
        #pragma unroll
        for (int l = 0; l < 2; l++) {
            int la = tid + l * 256;
            int ar = la >> 2;
            int ac = (la & 3) * 4;
            int grow = rowBase + ar;
            float4 v = make_float4(0.f, 0.f, 0.f, 0.f);
            if (grow < M)
                v = *reinterpret_cast<const float4*>(A + (size_t)grow * 128 + k0 + ac);
            As[ac + 0][ar] = v.x; As[ac + 1][ar] = v.y;
            As[ac + 2][ar] = v.z; As[ac + 3][ar] = v.w;
        }
        #pragma unroll
        for (int l = 0; l < 2; l++) {
            int lb = tid + l * 256;
            int br = lb >> 5;
            int bc = (lb & 31) * 4;
            *reinterpret_cast<float4*>(&Bs[br][bc]) =
                *reinterpret_cast<const float4*>(B + (size_t)(k0 + br) * 128 + bc);
        }
        __syncthreads();

        #pragma unroll
        for (int k = 0; k < 16; k++) {
            float ra[8], rb[8];
            #pragma unroll
            for (int i = 0; i < 8; i++) ra[i] = As[k][ty * 8 + i];
            #pragma unroll
            for (int j = 0; j < 8; j++) rb[j] = Bs[k][tx * 8 + j];
            #pragma unroll
            for (int i = 0; i < 8; i++)
                #pragma unroll
                for (int j = 0; j < 8; j++) acc[i][j] += ra[i] * rb[j];
        }
        __syncthreads();
    }

    #pragma unroll
    for (int i = 0; i < 8; i++) {
        int grow = rowBase + ty * 8 + i;
        if (grow >= M) break;
        float sc = __ldg(dinv + grow);
        #pragma unroll
        for (int j = 0; j < 8; j += 4) {
            float4 v = make_float4(acc[i][j] * sc, acc[i][j+1] * sc,
                                   acc[i][j+2] * sc, acc[i][j+3] * sc);
            *reinterpret_cast<float4*>(C + (size_t)grow * 128 + tx * 8 + j) = v;
        }
    }
}

// ---------------- pull-mode aggregation + bias + relu ----------------
// out[d] = relu( dinv[d] * (hs[d] + sum_{s in N(d)} hs[s]) + bias )
// One warp per node; lane owns 4 consecutive features.
__global__ __launch_bounds__(256) void agg_kernel(
    const float* __restrict__ hs, const int* __restrict__ csr,
    const int* __restrict__ rowptr, const float* __restrict__ dinv,
    const float* __restrict__ bias, float* __restrict__ out, int N)
{
    int w = (blockIdx.x * blockDim.x + threadIdx.x) >> 5;
    if (w >= N) return;
    int lane = threadIdx.x & 31;

    const float4* hs4 = reinterpret_cast<const float4*>(hs);
    int start = __ldg(rowptr + w);
    int end   = __ldg(rowptr + w + 1);

    float4 acc = hs4[(size_t)w * 32 + lane];   // self loop
    int j = start;
    for (; j + 4 <= end; j += 4) {
        int s0 = __ldg(csr + j);
        int s1 = __ldg(csr + j + 1);
        int s2 = __ldg(csr + j + 2);
        int s3 = __ldg(csr + j + 3);
        float4 v0 = hs4[(size_t)s0 * 32 + lane];
        float4 v1 = hs4[(size_t)s1 * 32 + lane];
        float4 v2 = hs4[(size_t)s2 * 32 + lane];
        float4 v3 = hs4[(size_t)s3 * 32 + lane];
        acc.x += (v0.x + v1.x) + (v2.x + v3.x);
        acc.y += (v0.y + v1.y) + (v2.y + v3.y);
        acc.z += (v0.z + v1.z) + (v2.z + v3.z);
        acc.w += (v0.w + v1.w) + (v2.w + v3.w);
    }
    for (; j < end; j++) {
        int s = __ldg(csr + j);
        float4 v = hs4[(size_t)s * 32 + lane];
        acc.x += v.x; acc.y += v.y; acc.z += v.z; acc.w += v.w;
    }

    float di = __ldg(dinv + w);
    float4 bv = reinterpret_cast<const float4*>(bias)[lane];
    float4 r;
    r.x = fmaxf(fmaf(acc.x, di, bv.x), 0.f);
    r.y = fmaxf(fmaf(acc.y, di, bv.y), 0.f);
    r.z = fmaxf(fmaf(acc.z, di, bv.z), 0.f);
    r.w = fmaxf(fmaf(acc.w, di, bv.w), 0.f);
    reinterpret_cast<float4*>(out)[(size_t)w * 32 + lane] = r;
}

// ---------------- pooling over sorted batch ids ----------------
#define POOL_ROWS 512
__global__ void pool_kernel(
    const float* __restrict__ a, const int* __restrict__ batch,
    float* __restrict__ g, float* __restrict__ cnt, int N)
{
    int c = threadIdx.x;
    int row0 = blockIdx.x * POOL_ROWS;
    if (row0 >= N) return;
    int row1 = min(row0 + POOL_ROWS, N);

    int cur = __ldg(batch + row0);
    float acc = 0.f, count = 0.f;
    for (int r = row0; r < row1; r++) {
        int b = __ldg(batch + r);
        if (b != cur) {
            atomicAdd(&g[cur * HID + c], acc);
            if (c == 0) atomicAdd(&cnt[cur], count);
            acc = 0.f; count = 0.f; cur = b;
        }
        acc += a[(size_t)r * HID + c];
        count += 1.f;
    }
    atomicAdd(&g[cur * HID + c], acc);
    if (c == 0) atomicAdd(&cnt[cur], count);
}

// ---------------- final MLP ----------------
__global__ void mlp_kernel(
    const float* __restrict__ g, const float* __restrict__ cnt,
    const float* __restrict__ Wc1, const float* __restrict__ bc1,
    const float* __restrict__ Wc2, const float* __restrict__ bc2,
    float* __restrict__ out)
{
    __shared__ float gr[HID], z[HID];
    int b = blockIdx.x;
    int t = threadIdx.x;
    float c = cnt[b];
    c = (c < 1.f) ? 1.f : c;
    gr[t] = g[b * HID + t] / c;
    __syncthreads();

    float acc = bc1[t];
    for (int k = 0; k < HID; k++) acc += gr[k] * Wc1[k * HID + t];
    z[t] = fmaxf(acc, 0.f);
    __syncthreads();

    if (t < NC) {
        float o = bc2[t];
        for (int k = 0; k < HID; k++) o += z[k] * Wc2[k * NC + t];
        out[b * NC + t] = o;
    }
}

// ---------------- launch ----------------
extern "C" void kernel_launch(void* const* d_in, const int* in_sizes, int n_in,
                              void* d_out, int out_size)
{
    const float* x    = (const float*)d_in[0];
    const int*   edge = (const int*)  d_in[1];
    const int*   batc = (const int*)  d_in[2];
    const float* W1   = (const float*)d_in[3];
    const float* b1   = (const float*)d_in[4];
    const float* W2   = (const float*)d_in[5];
    const float* b2   = (const float*)d_in[6];
    const float* Wc1  = (const float*)d_in[7];
    const float* bc1  = (const float*)d_in[8];
    const float* Wc2  = (const float*)d_in[9];
    const float* bc2  = (const float*)d_in[10];

    const int N = in_sizes[0] / HID;
    const int E = in_sizes[1] / 2;
    const int* src = edge;
    const int* dst = edge + E;

    int *degi_p, *rowptr_p, *cursor_p, *csr_p;
    float *dinv_p, *h_p, *a_p, *g_p, *cnt_p;
    cudaGetSymbolAddress((void**)&degi_p,   g_degi);
    cudaGetSymbolAddress((void**)&rowptr_p, g_rowptr);
    cudaGetSymbolAddress((void**)&cursor_p, g_cursor);
    cudaGetSymbolAddress((void**)&csr_p,    g_csr);
    cudaGetSymbolAddress((void**)&dinv_p,   g_dinv);
    cudaGetSymbolAddress((void**)&h_p,      g_h);
    cudaGetSymbolAddress((void**)&a_p,      g_a);
    cudaGetSymbolAddress((void**)&g_p,      g_pool);
    cudaGetSymbolAddress((void**)&cnt_p,    g_cnt);

    // ---- CSR build + normalization (once, reused by both layers) ----
    cudaMemsetAsync(degi_p, 0, N * sizeof(int));
    hist_kernel<<<(E + 255) / 256, 256>>>(dst, degi_p, E);
    scan_kernel<<<1, 1024>>>(degi_p, rowptr_p, N);
    cudaMemcpyAsync(cursor_p, rowptr_p, N * sizeof(int), cudaMemcpyDeviceToDevice);
    fill_kernel<<<(E + 255) / 256, 256>>>(src, dst, cursor_p, csr_p, E);
    dinv_kernel<<<(N + 255) / 256, 256>>>(degi_p, dinv_p, N);

    const int aggGrid = (N * 32 + 255) / 256;

    // ---- layer 1 ----
    sgemm128<<<(N + 127) / 128, 256>>>(x, W1, dinv_p, h_p, N);
    agg_kernel<<<aggGrid, 256>>>(h_p, csr_p, rowptr_p, dinv_p, b1, a_p, N);

    // ---- layer 2 ----
    sgemm128<<<(N + 127) / 128, 256>>>(a_p, W2, dinv_p, h_p, N);
    agg_kernel<<<aggGrid, 256>>>(h_p, csr_p, rowptr_p, dinv_p, b2, a_p, N);

    // ---- pooling + MLP ----
    cudaMemsetAsync(g_p, 0, NG * HID * sizeof(float));
    cudaMemsetAsync(cnt_p, 0, NG * sizeof(float));
    pool_kernel<<<(N + POOL_ROWS - 1) / POOL_ROWS, HID>>>(a_p, batc, g_p, cnt_p, N);
    mlp_kernel<<<NG, HID>>>(g_p, cnt_p, Wc1, bc1, Wc2, bc2, (float*)d_out);
}

// round 4
// speedup vs baseline: 2.4982x; 1.0472x over previous
#include <cuda_runtime.h>
#include <cuda_fp16.h>
#include <math.h>

#define MAXN 50000
#define MAXE 1700000
#define HID 128
#define NG 64
#define NC 10

// ---------------- static device scratch ----------------
__device__ int    g_degi[MAXN];
__device__ int    g_rowptr[MAXN + 1];
__device__ int    g_cursor[MAXN];
__device__ int    g_csr[MAXE];
__device__ float  g_dinv[MAXN];
__device__ __half g_h [(size_t)MAXN * HID];   // (x @ W) * dinv[row], fp16
__device__ float  g_a [(size_t)MAXN * HID];   // layer activation (fp32)
__device__ float  g_pool[NG * HID];
__device__ float  g_cnt[NG];

// ---------------- degree histogram ----------------
__global__ void hist_kernel(const int* __restrict__ dst, int* __restrict__ deg, int E) {
    int i = blockIdx.x * blockDim.x + threadIdx.x;
    if (i < E) atomicAdd(&deg[dst[i]], 1);
}

// ---------------- single-block exclusive scan of degrees -> rowptr ----------------
__global__ __launch_bounds__(1024) void scan_kernel(
    const int* __restrict__ deg, int* __restrict__ rowptr, int N)
{
    const int T = 1024;
    int t = threadIdx.x;
    int C = (N + T - 1) / T;
    int lo = t * C;
    int hi = min(lo + C, N);
    if (lo > N) lo = N;
    if (hi < lo) hi = lo;

    int s = 0;
    for (int i = lo; i < hi; i++) s += deg[i];

    int lane = t & 31, wid = t >> 5;
    int v = s;
    #pragma unroll
    for (int o = 1; o < 32; o <<= 1) {
        int u = __shfl_up_sync(0xffffffffu, v, o);
        if (lane >= o) v += u;
    }
    __shared__ int wsum[32];
    if (lane == 31) wsum[wid] = v;
    __syncthreads();
    if (wid == 0) {
        int w = wsum[lane];
        #pragma unroll
        for (int o = 1; o < 32; o <<= 1) {
            int u = __shfl_up_sync(0xffffffffu, w, o);
            if (lane >= o) w += u;
        }
        wsum[lane] = w;
    }
    __syncthreads();
    int excl = v - s + (wid > 0 ? wsum[wid - 1] : 0);

    int run = excl;
    for (int i = lo; i < hi; i++) { rowptr[i] = run; run += deg[i]; }
    if (hi == N) rowptr[N] = run;
}

// ---------------- CSR fill ----------------
__global__ void fill_kernel(const int* __restrict__ src, const int* __restrict__ dst,
                            int* __restrict__ cursor, int* __restrict__ csr, int E)
{
    int i = blockIdx.x * blockDim.x + threadIdx.x;
    if (i < E) {
        int d = dst[i];
        int p = atomicAdd(&cursor[d], 1);
        csr[p] = src[i];
    }
}

__global__ void dinv_kernel(const int* __restrict__ deg, float* __restrict__ dinv, int N) {
    int i = blockIdx.x * blockDim.x + threadIdx.x;
    if (i < N) dinv[i] = rsqrtf((float)deg[i] + 1.0f);
}

// ---------------- SGEMM: H[M,128] = half((A[M,128] @ B[128,128]) * dinv[row]) ----------------
__global__ __launch_bounds__(256, 2) void sgemm128(
    const float* __restrict__ A, const float* __restrict__ B,
    const float* __restrict__ dinv, __half* __restrict__ C, int M)
{
    __shared__ float As[16][132];
    __shared__ float Bs[16][128];

    const int tid = threadIdx.x;
    const int tx = tid & 15;
    const int ty = tid >> 4;
    const int rowBase = blockIdx.x * 128;

    float acc[8][8];
    #pragma unroll
    for (int i = 0; i < 8; i++)
        #pragma unroll
        for (int j = 0; j < 8; j++) acc[i][j] = 0.f;

    for (int k0 = 0; k0 < 128; k0 += 16) {
        #pragma unroll
        for (int l = 0; l < 2; l++) {
            int la = tid + l * 256;
            int ar = la >> 2;
            int ac = (la & 3) * 4;
            int grow = rowBase + ar;
            float4 v = make_float4(0.f, 0.f, 0.f, 0.f);
            if (grow < M)
                v = *reinterpret_cast<const float4*>(A + (size_t)grow * 128 + k0 + ac);
            As[ac + 0][ar] = v.x; As[ac + 1][ar] = v.y;
            As[ac + 2][ar] = v.z; As[ac + 3][ar] = v.w;
        }
        #pragma unroll
        for (int l = 0; l < 2; l++) {
            int lb = tid + l * 256;
            int br = lb >> 5;
            int bc = (lb & 31) * 4;
            *reinterpret_cast<float4*>(&Bs[br][bc]) =
                *reinterpret_cast<const float4*>(B + (size_t)(k0 + br) * 128 + bc);
        }
        __syncthreads();

        #pragma unroll
        for (int k = 0; k < 16; k++) {
            float ra[8], rb[8];
            #pragma unroll
            for (int i = 0; i < 8; i++) ra[i] = As[k][ty * 8 + i];
            #pragma unroll
            for (int j = 0; j < 8; j++) rb[j] = Bs[k][tx * 8 + j];
            #pragma unroll
            for (int i = 0; i < 8; i++)
                #pragma unroll
                for (int j = 0; j < 8; j++) acc[i][j] += ra[i] * rb[j];
        }
        __syncthreads();
    }

    #pragma unroll
    for (int i = 0; i < 8; i++) {
        int grow = rowBase + ty * 8 + i;
        if (grow >= M) break;
        float sc = __ldg(dinv + grow);
        // 8 floats -> 8 halves = 4 half2 = one uint4 store
        __half2 hv[4];
        #pragma unroll
        for (int j = 0; j < 4; j++)
            hv[j] = __floats2half2_rn(acc[i][2*j] * sc, acc[i][2*j+1] * sc);
        uint4 pack = *reinterpret_cast<uint4*>(hv);
        *reinterpret_cast<uint4*>(C + (size_t)grow * 128 + tx * 8) = pack;
    }
}

// ---------------- pull-mode aggregation + bias + relu (fp16 gather, fp32 accum) ----------------
// out[d] = relu( dinv[d] * (hs[d] + sum_{s in N(d)} hs[s]) + bias )
// One warp per node; lane owns 4 consecutive features (= 2 half2 = 8 bytes).
__global__ __launch_bounds__(256) void agg_kernel(
    const __half* __restrict__ hs, const int* __restrict__ csr,
    const int* __restrict__ rowptr, const float* __restrict__ dinv,
    const float* __restrict__ bias, float* __restrict__ out, int N)
{
    int w = (blockIdx.x * blockDim.x + threadIdx.x) >> 5;
    if (w >= N) return;
    int lane = threadIdx.x & 31;

    const __half2* hs2 = reinterpret_cast<const __half2*>(hs);  // row = 64 half2
    int start = __ldg(rowptr + w);
    int end   = __ldg(rowptr + w + 1);

    float acc0, acc1, acc2, acc3;
    {   // self loop
        __half2 a = hs2[(size_t)w * 64 + lane * 2];
        __half2 b = hs2[(size_t)w * 64 + lane * 2 + 1];
        float2 fa = __half22float2(a), fb = __half22float2(b);
        acc0 = fa.x; acc1 = fa.y; acc2 = fb.x; acc3 = fb.y;
    }

    int j = start;
    for (; j + 4 <= end; j += 4) {
        int s0 = __ldg(csr + j);
        int s1 = __ldg(csr + j + 1);
        int s2 = __ldg(csr + j + 2);
        int s3 = __ldg(csr + j + 3);
        float2 p0a = __half22float2(hs2[(size_t)s0 * 64 + lane * 2]);
        float2 p0b = __half22float2(hs2[(size_t)s0 * 64 + lane * 2 + 1]);
        float2 p1a = __half22float2(hs2[(size_t)s1 * 64 + lane * 2]);
        float2 p1b = __half22float2(hs2[(size_t)s1 * 64 + lane * 2 + 1]);
        float2 p2a = __half22float2(hs2[(size_t)s2 * 64 + lane * 2]);
        float2 p2b = __half22float2(hs2[(size_t)s2 * 64 + lane * 2 + 1]);
        float2 p3a = __half22float2(hs2[(size_t)s3 * 64 + lane * 2]);
        float2 p3b = __half22float2(hs2[(size_t)s3 * 64 + lane * 2 + 1]);
        acc0 += (p0a.x + p1a.x) + (p2a.x + p3a.x);
        acc1 += (p0a.y + p1a.y) + (p2a.y + p3a.y);
        acc2 += (p0b.x + p1b.x) + (p2b.x + p3b.x);
        acc3 += (p0b.y + p1b.y) + (p2b.y + p3b.y);
    }
    for (; j < end; j++) {
        int s = __ldg(csr + j);
        float2 pa = __half22float2(hs2[(size_t)s * 64 + lane * 2]);
        float2 pb = __half22float2(hs2[(size_t)s * 64 + lane * 2 + 1]);
        acc0 += pa.x; acc1 += pa.y; acc2 += pb.x; acc3 += pb.y;
    }

    float di = __ldg(dinv + w);
    float4 bv = reinterpret_cast<const float4*>(bias)[lane];
    float4 r;
    r.x = fmaxf(fmaf(acc0, di, bv.x), 0.f);
    r.y = fmaxf(fmaf(acc1, di, bv.y), 0.f);
    r.z = fmaxf(fmaf(acc2, di, bv.z), 0.f);
    r.w = fmaxf(fmaf(acc3, di, bv.w), 0.f);
    reinterpret_cast<float4*>(out)[(size_t)w * 32 + lane] = r;
}

// ---------------- pooling over sorted batch ids ----------------
#define POOL_ROWS 512
__global__ void pool_kernel(
    const float* __restrict__ a, const int* __restrict__ batch,
    float* __restrict__ g, float* __restrict__ cnt, int N)
{
    int c = threadIdx.x;
    int row0 = blockIdx.x * POOL_ROWS;
    if (row0 >= N) return;
    int row1 = min(row0 + POOL_ROWS, N);

    int cur = __ldg(batch + row0);
    float acc = 0.f, count = 0.f;
    for (int r = row0; r < row1; r++) {
        int b = __ldg(batch + r);
        if (b != cur) {
            atomicAdd(&g[cur * HID + c], acc);
            if (c == 0) atomicAdd(&cnt[cur], count);
            acc = 0.f; count = 0.f; cur = b;
        }
        acc += a[(size_t)r * HID + c];
        count += 1.f;
    }
    atomicAdd(&g[cur * HID + c], acc);
    if (c == 0) atomicAdd(&cnt[cur], count);
}

// ---------------- final MLP ----------------
__global__ void mlp_kernel(
    const float* __restrict__ g, const float* __restrict__ cnt,
    const float* __restrict__ Wc1, const float* __restrict__ bc1,
    const float* __restrict__ Wc2, const float* __restrict__ bc2,
    float* __restrict__ out)
{
    __shared__ float gr[HID], z[HID];
    int b = blockIdx.x;
    int t = threadIdx.x;
    float c = cnt[b];
    c = (c < 1.f) ? 1.f : c;
    gr[t] = g[b * HID + t] / c;
    __syncthreads();

    float acc = bc1[t];
    for (int k = 0; k < HID; k++) acc += gr[k] * Wc1[k * HID + t];
    z[t] = fmaxf(acc, 0.f);
    __syncthreads();

    if (t < NC) {
        float o = bc2[t];
        for (int k = 0; k < HID; k++) o += z[k] * Wc2[k * NC + t];
        out[b * NC + t] = o;
    }
}

// ---------------- launch ----------------
extern "C" void kernel_launch(void* const* d_in, const int* in_sizes, int n_in,
                              void* d_out, int out_size)
{
    const float* x    = (const float*)d_in[0];
    const int*   edge = (const int*)  d_in[1];
    const int*   batc = (const int*)  d_in[2];
    const float* W1   = (const float*)d_in[3];
    const float* b1   = (const float*)d_in[4];
    const float* W2   = (const float*)d_in[5];
    const float* b2   = (const float*)d_in[6];
    const float* Wc1  = (const float*)d_in[7];
    const float* bc1  = (const float*)d_in[8];
    const float* Wc2  = (const float*)d_in[9];
    const float* bc2  = (const float*)d_in[10];

    const int N = in_sizes[0] / HID;
    const int E = in_sizes[1] / 2;
    const int* src = edge;
    const int* dst = edge + E;

    int *degi_p, *rowptr_p, *cursor_p, *csr_p;
    float *dinv_p, *a_p, *g_p, *cnt_p;
    __half* h_p;
    cudaGetSymbolAddress((void**)&degi_p,   g_degi);
    cudaGetSymbolAddress((void**)&rowptr_p, g_rowptr);
    cudaGetSymbolAddress((void**)&cursor_p, g_cursor);
    cudaGetSymbolAddress((void**)&csr_p,    g_csr);
    cudaGetSymbolAddress((void**)&dinv_p,   g_dinv);
    cudaGetSymbolAddress((void**)&h_p,      g_h);
    cudaGetSymbolAddress((void**)&a_p,      g_a);
    cudaGetSymbolAddress((void**)&g_p,      g_pool);
    cudaGetSymbolAddress((void**)&cnt_p,    g_cnt);

    // ---- CSR build + normalization (once, reused by both layers) ----
    cudaMemsetAsync(degi_p, 0, N * sizeof(int));
    hist_kernel<<<(E + 255) / 256, 256>>>(dst, degi_p, E);
    scan_kernel<<<1, 1024>>>(degi_p, rowptr_p, N);
    cudaMemcpyAsync(cursor_p, rowptr_p, N * sizeof(int), cudaMemcpyDeviceToDevice);
    fill_kernel<<<(E + 255) / 256, 256>>>(src, dst, cursor_p, csr_p, E);
    dinv_kernel<<<(N + 255) / 256, 256>>>(degi_p, dinv_p, N);

    const int aggGrid = (N * 32 + 255) / 256;

    // ---- layer 1 ----
    sgemm128<<<(N + 127) / 128, 256>>>(x, W1, dinv_p, h_p, N);
    agg_kernel<<<aggGrid, 256>>>(h_p, csr_p, rowptr_p, dinv_p, b1, a_p, N);

    // ---- layer 2 ----
    sgemm128<<<(N + 127) / 128, 256>>>(a_p, W2, dinv_p, h_p, N);
    agg_kernel<<<aggGrid, 256>>>(h_p, csr_p, rowptr_p, dinv_p, b2, a_p, N);

    // ---- pooling + MLP ----
    cudaMemsetAsync(g_p, 0, NG * HID * sizeof(float));
    cudaMemsetAsync(cnt_p, 0, NG * sizeof(float));
    pool_kernel<<<(N + POOL_ROWS - 1) / POOL_ROWS, HID>>>(a_p, batc, g_p, cnt_p, N);
    mlp_kernel<<<NG, HID>>>(g_p, cnt_p, Wc1, bc1, Wc2, bc2, (float*)d_out);
}

// round 6
// speedup vs baseline: 3.1356x; 1.2552x over previous
#include <cuda_runtime.h>
#include <cuda_fp16.h>
#include <math.h>

#define MAXN 50000
#define MAXE 1700000
#define HID 128
#define NG 64
#define NC 10

// ---------------- static device scratch ----------------
__device__ int    g_degi[MAXN];
__device__ int    g_rowptr[MAXN + 1];
__device__ int    g_cursor[MAXN];
__device__ int    g_csr[MAXE];
__device__ float  g_dinv[MAXN];
__device__ __half g_h [(size_t)MAXN * HID];   // GEMM out * dinv[row], fp16
__device__ __half g_ah[(size_t)MAXN * HID];   // agg out (activation), fp16
__device__ float  g_pool[NG * HID];
__device__ float  g_cnt[NG];

// ---------------- degree histogram ----------------
__global__ void hist_kernel(const int* __restrict__ dst, int* __restrict__ deg, int E) {
    int i = blockIdx.x * blockDim.x + threadIdx.x;
    if (i < E) atomicAdd(&deg[dst[i]], 1);
}

// ---------------- single-block exclusive scan of degrees -> rowptr ----------------
__global__ __launch_bounds__(1024) void scan_kernel(
    const int* __restrict__ deg, int* __restrict__ rowptr, int N)
{
    const int T = 1024;
    int t = threadIdx.x;
    int C = (N + T - 1) / T;
    int lo = t * C;
    int hi = min(lo + C, N);
    if (lo > N) lo = N;
    if (hi < lo) hi = lo;

    int s = 0;
    for (int i = lo; i < hi; i++) s += deg[i];

    int lane = t & 31, wid = t >> 5;
    int v = s;
    #pragma unroll
    for (int o = 1; o < 32; o <<= 1) {
        int u = __shfl_up_sync(0xffffffffu, v, o);
        if (lane >= o) v += u;
    }
    __shared__ int wsum[32];
    if (lane == 31) wsum[wid] = v;
    __syncthreads();
    if (wid == 0) {
        int w = wsum[lane];
        #pragma unroll
        for (int o = 1; o < 32; o <<= 1) {
            int u = __shfl_up_sync(0xffffffffu, w, o);
            if (lane >= o) w += u;
        }
        wsum[lane] = w;
    }
    __syncthreads();
    int excl = v - s + (wid > 0 ? wsum[wid - 1] : 0);

    int run = excl;
    for (int i = lo; i < hi; i++) { rowptr[i] = run; run += deg[i]; }
    if (hi == N) rowptr[N] = run;
}

// ---------------- CSR fill ----------------
__global__ void fill_kernel(const int* __restrict__ src, const int* __restrict__ dst,
                            int* __restrict__ cursor, int* __restrict__ csr, int E)
{
    int i = blockIdx.x * blockDim.x + threadIdx.x;
    if (i < E) {
        int d = dst[i];
        int p = atomicAdd(&cursor[d], 1);
        csr[p] = src[i];
    }
}

__global__ void dinv_kernel(const int* __restrict__ deg, float* __restrict__ dinv, int N) {
    int i = blockIdx.x * blockDim.x + threadIdx.x;
    if (i < N) dinv[i] = rsqrtf((float)deg[i] + 1.0f);
}

// ---------------- Tensor-core GEMM: C[M,128] = half((A @ W) * dinv[row]) ----------------
// A: fp32 (layer 1, template A_FP32=true) or fp16 (layer 2). W: fp32 row-major 128x128,
// converted to fp16 in smem. Whole K=128 resident; one __syncthreads.
// 256 threads = 8 warps; warp tile 64(m) x 32(n); mma.m16n8k16 fp16->fp32.
#define APAD 136   // halves per smem row (272 B: row-to-row bank offset = 4 -> conflict-free)

template<bool A_FP32>
__global__ __launch_bounds__(256) void hgemm128(
    const void* __restrict__ Aptr, const float* __restrict__ W,
    const float* __restrict__ dinv, __half* __restrict__ C, int M)
{
    extern __shared__ __half sm[];
    __half* As = sm;                 // [128][APAD]
    __half* Bs = sm + 128 * APAD;    // [128][APAD]  (k-major: Bs[k][n])

    const int tid = threadIdx.x;
    const int rowBase = blockIdx.x * 128;

    // ---- load A tile (convert fp32->fp16 if needed) ----
    #pragma unroll
    for (int i = tid; i < 4096; i += 256) {
        int r = i >> 5;            // 0..127
        int c = (i & 31) * 4;      // 0..124
        int gr = rowBase + r;
        if (A_FP32) {
            float4 v = make_float4(0.f, 0.f, 0.f, 0.f);
            if (gr < M)
                v = *reinterpret_cast<const float4*>((const float*)Aptr + (size_t)gr * 128 + c);
            __half2 h0 = __floats2half2_rn(v.x, v.y);
            __half2 h1 = __floats2half2_rn(v.z, v.w);
            *reinterpret_cast<__half2*>(&As[r * APAD + c])     = h0;
            *reinterpret_cast<__half2*>(&As[r * APAD + c + 2]) = h1;
        } else {
            uint2 v = make_uint2(0u, 0u);
            if (gr < M)
                v = *reinterpret_cast<const uint2*>((const __half*)Aptr + (size_t)gr * 128 + c);
            *reinterpret_cast<uint2*>(&As[r * APAD + c]) = v;
        }
    }
    // ---- load W (fp32 -> fp16), k-major ----
    #pragma unroll
    for (int i = tid; i < 4096; i += 256) {
        int r = i >> 5;
        int c = (i & 31) * 4;
        float4 v = *reinterpret_cast<const float4*>(W + (size_t)r * 128 + c);
        __half2 h0 = __floats2half2_rn(v.x, v.y);
        __half2 h1 = __floats2half2_rn(v.z, v.w);
        *reinterpret_cast<__half2*>(&Bs[r * APAD + c])     = h0;
        *reinterpret_cast<__half2*>(&Bs[r * APAD + c + 2]) = h1;
    }
    __syncthreads();

    const int wid  = tid >> 5;
    const int lane = tid & 31;
    const int wm = wid & 1;           // 0..1 -> m offset 0/64
    const int wn = wid >> 1;          // 0..3 -> n offset 0/32/64/96... wait 4 warps x 32 = 128 ok
    const int m0 = wm * 64;
    const int n0 = wn * 32;
    const int g = lane >> 2;          // 0..7
    const int t = lane & 3;           // 0..3

    float acc[4][4][4];
    #pragma unroll
    for (int mi = 0; mi < 4; mi++)
        #pragma unroll
        for (int ni = 0; ni < 4; ni++)
            #pragma unroll
            for (int q = 0; q < 4; q++) acc[mi][ni][q] = 0.f;

    #pragma unroll
    for (int ks = 0; ks < 8; ks++) {
        const int k0 = ks * 16;
        // A fragments: 4 m-tiles of 16 rows
        unsigned afr[4][4];
        #pragma unroll
        for (int mi = 0; mi < 4; mi++) {
            int ra = m0 + mi * 16;
            afr[mi][0] = *reinterpret_cast<const unsigned*>(&As[(ra + g)     * APAD + k0 + 2 * t]);
            afr[mi][1] = *reinterpret_cast<const unsigned*>(&As[(ra + 8 + g) * APAD + k0 + 2 * t]);
            afr[mi][2] = *reinterpret_cast<const unsigned*>(&As[(ra + g)     * APAD + k0 + 8 + 2 * t]);
            afr[mi][3] = *reinterpret_cast<const unsigned*>(&As[(ra + 8 + g) * APAD + k0 + 8 + 2 * t]);
        }
        // B fragments: 4 n-tiles of 8 cols (Bs is k-major -> gather 2B elems, pack)
        unsigned bfr[4][2];
        #pragma unroll
        for (int ni = 0; ni < 4; ni++) {
            int col = n0 + ni * 8 + g;
            __half x0 = Bs[(k0 + 2 * t)     * APAD + col];
            __half x1 = Bs[(k0 + 2 * t + 1) * APAD + col];
            __half x2 = Bs[(k0 + 8 + 2 * t) * APAD + col];
            __half x3 = Bs[(k0 + 9 + 2 * t) * APAD + col];
            __half2 p0 = __halves2half2(x0, x1);
            __half2 p1 = __halves2half2(x2, x3);
            bfr[ni][0] = *reinterpret_cast<unsigned*>(&p0);
            bfr[ni][1] = *reinterpret_cast<unsigned*>(&p1);
        }
        #pragma unroll
        for (int mi = 0; mi < 4; mi++)
            #pragma unroll
            for (int ni = 0; ni < 4; ni++) {
                asm volatile(
                    "mma.sync.aligned.m16n8k16.row.col.f32.f16.f16.f32 "
                    "{%0,%1,%2,%3}, {%4,%5,%6,%7}, {%8,%9}, {%0,%1,%2,%3};\n"
                    : "+f"(acc[mi][ni][0]), "+f"(acc[mi][ni][1]),
                      "+f"(acc[mi][ni][2]), "+f"(acc[mi][ni][3])
                    : "r"(afr[mi][0]), "r"(afr[mi][1]), "r"(afr[mi][2]), "r"(afr[mi][3]),
                      "r"(bfr[ni][0]), "r"(bfr[ni][1]));
            }
    }

    // ---- epilogue: scale by dinv[row], convert fp16, store ----
    #pragma unroll
    for (int mi = 0; mi < 4; mi++) {
        int r1 = rowBase + m0 + mi * 16 + g;
        int r2 = r1 + 8;
        float s1 = (r1 < M) ? __ldg(dinv + r1) : 0.f;
        float s2 = (r2 < M) ? __ldg(dinv + r2) : 0.f;
        #pragma unroll
        for (int ni = 0; ni < 4; ni++) {
            int col = n0 + ni * 8 + 2 * t;
            if (r1 < M) {
                __half2 hv = __floats2half2_rn(acc[mi][ni][0] * s1, acc[mi][ni][1] * s1);
                *reinterpret_cast<__half2*>(C + (size_t)r1 * 128 + col) = hv;
            }
            if (r2 < M) {
                __half2 hv = __floats2half2_rn(acc[mi][ni][2] * s2, acc[mi][ni][3] * s2);
                *reinterpret_cast<__half2*>(C + (size_t)r2 * 128 + col) = hv;
            }
        }
    }
}

// ---------------- pull-mode aggregation + bias + relu (fp16 in/out, fp32 accum) ----------------
// out[d] = relu( dinv[d] * (hs[d] + sum_{s in N(d)} hs[s]) + bias )
// One warp per node; lane owns 4 consecutive features (8 B -> one LDG.64).
__global__ __launch_bounds__(256) void agg_kernel(
    const __half* __restrict__ hs, const int* __restrict__ csr,
    const int* __restrict__ rowptr, const float* __restrict__ dinv,
    const float* __restrict__ bias, __half* __restrict__ out, int N)
{
    int w = (blockIdx.x * blockDim.x + threadIdx.x) >> 5;
    if (w >= N) return;
    int lane = threadIdx.x & 31;

    const uint2* hsv = reinterpret_cast<const uint2*>(hs);  // row = 32 uint2
    int start = __ldg(rowptr + w);
    int end   = __ldg(rowptr + w + 1);

    float acc0, acc1, acc2, acc3;
    {   // self loop
        uint2 u = hsv[(size_t)w * 32 + lane];
        float2 fa = __half22float2(*reinterpret_cast<__half2*>(&u.x));
        float2 fb = __half22float2(*reinterpret_cast<__half2*>(&u.y));
        acc0 = fa.x; acc1 = fa.y; acc2 = fb.x; acc3 = fb.y;
    }

    int j = start;
    for (; j + 4 <= end; j += 4) {
        int s0 = __ldg(csr + j);
        int s1 = __ldg(csr + j + 1);
        int s2 = __ldg(csr + j + 2);
        int s3 = __ldg(csr + j + 3);
        uint2 u0 = hsv[(size_t)s0 * 32 + lane];
        uint2 u1 = hsv[(size_t)s1 * 32 + lane];
        uint2 u2 = hsv[(size_t)s2 * 32 + lane];
        uint2 u3 = hsv[(size_t)s3 * 32 + lane];
        float2 a0 = __half22float2(*reinterpret_cast<__half2*>(&u0.x));
        float2 b0 = __half22float2(*reinterpret_cast<__half2*>(&u0.y));
        float2 a1 = __half22float2(*reinterpret_cast<__half2*>(&u1.x));
        float2 b1 = __half22float2(*reinterpret_cast<__half2*>(&u1.y));
        float2 a2 = __half22float2(*reinterpret_cast<__half2*>(&u2.x));
        float2 b2 = __half22float2(*reinterpret_cast<__half2*>(&u2.y));
        float2 a3 = __half22float2(*reinterpret_cast<__half2*>(&u3.x));
        float2 b3 = __half22float2(*reinterpret_cast<__half2*>(&u3.y));
        acc0 += (a0.x + a1.x) + (a2.x + a3.x);
        acc1 += (a0.y + a1.y) + (a2.y + a3.y);
        acc2 += (b0.x + b1.x) + (b2.x + b3.x);
        acc3 += (b0.y + b1.y) + (b2.y + b3.y);
    }
    for (; j < end; j++) {
        int s = __ldg(csr + j);
        uint2 u = hsv[(size_t)s * 32 + lane];
        float2 fa = __half22float2(*reinterpret_cast<__half2*>(&u.x));
        float2 fb = __half22float2(*reinterpret_cast<__half2*>(&u.y));
        acc0 += fa.x; acc1 += fa.y; acc2 += fb.x; acc3 += fb.y;
    }

    float di = __ldg(dinv + w);
    float4 bv = reinterpret_cast<const float4*>(bias)[lane];
    float r0 = fmaxf(fmaf(acc0, di, bv.x), 0.f);
    float r1 = fmaxf(fmaf(acc1, di, bv.y), 0.f);
    float r2 = fmaxf(fmaf(acc2, di, bv.z), 0.f);
    float r3 = fmaxf(fmaf(acc3, di, bv.w), 0.f);
    __half2 h0 = __floats2half2_rn(r0, r1);
    __half2 h1 = __floats2half2_rn(r2, r3);
    uint2 packed;
    packed.x = *reinterpret_cast<unsigned*>(&h0);
    packed.y = *reinterpret_cast<unsigned*>(&h1);
    reinterpret_cast<uint2*>(out)[(size_t)w * 32 + lane] = packed;
}

// ---------------- pooling over sorted batch ids (fp16 input) ----------------
#define POOL_ROWS 512
__global__ void pool_kernel(
    const __half* __restrict__ a, const int* __restrict__ batch,
    float* __restrict__ g, float* __restrict__ cnt, int N)
{
    int c = threadIdx.x;
    int row0 = blockIdx.x * POOL_ROWS;
    if (row0 >= N) return;
    int row1 = min(row0 + POOL_ROWS, N);

    int cur = __ldg(batch + row0);
    float acc = 0.f, count = 0.f;
    for (int r = row0; r < row1; r++) {
        int b = __ldg(batch + r);
        if (b != cur) {
            atomicAdd(&g[cur * HID + c], acc);
            if (c == 0) atomicAdd(&cnt[cur], count);
            acc = 0.f; count = 0.f; cur = b;
        }
        acc += __half2float(__ldg(a + (size_t)r * HID + c));
        count += 1.f;
    }
    atomicAdd(&g[cur * HID + c], acc);
    if (c == 0) atomicAdd(&cnt[cur], count);
}

// ---------------- final MLP ----------------
__global__ void mlp_kernel(
    const float* __restrict__ g, const float* __restrict__ cnt,
    const float* __restrict__ Wc1, const float* __restrict__ bc1,
    const float* __restrict__ Wc2, const float* __restrict__ bc2,
    float* __restrict__ out)
{
    __shared__ float gr[HID], z[HID];
    int b = blockIdx.x;
    int t = threadIdx.x;
    float c = cnt[b];
    c = (c < 1.f) ? 1.f : c;
    gr[t] = g[b * HID + t] / c;
    __syncthreads();

    float acc = bc1[t];
    for (int k = 0; k < HID; k++) acc += gr[k] * Wc1[k * HID + t];
    z[t] = fmaxf(acc, 0.f);
    __syncthreads();

    if (t < NC) {
        float o = bc2[t];
        for (int k = 0; k < HID; k++) o += z[k] * Wc2[k * NC + t];
        out[b * NC + t] = o;
    }
}

// ---------------- launch ----------------
extern "C" void kernel_launch(void* const* d_in, const int* in_sizes, int n_in,
                              void* d_out, int out_size)
{
    const float* x    = (const float*)d_in[0];
    const int*   edge = (const int*)  d_in[1];
    const int*   batc = (const int*)  d_in[2];
    const float* W1   = (const float*)d_in[3];
    const float* b1   = (const float*)d_in[4];
    const float* W2   = (const float*)d_in[5];
    const float* b2   = (const float*)d_in[6];
    const float* Wc1  = (const float*)d_in[7];
    const float* bc1  = (const float*)d_in[8];
    const float* Wc2  = (const float*)d_in[9];
    const float* bc2  = (const float*)d_in[10];

    const int N = in_sizes[0] / HID;
    const int E = in_sizes[1] / 2;
    const int* src = edge;
    const int* dst = edge + E;

    int *degi_p, *rowptr_p, *cursor_p, *csr_p;
    float *dinv_p, *g_p, *cnt_p;
    __half *h_p, *ah_p;
    cudaGetSymbolAddress((void**)&degi_p,   g_degi);
    cudaGetSymbolAddress((void**)&rowptr_p, g_rowptr);
    cudaGetSymbolAddress((void**)&cursor_p, g_cursor);
    cudaGetSymbolAddress((void**)&csr_p,    g_csr);
    cudaGetSymbolAddress((void**)&dinv_p,   g_dinv);
    cudaGetSymbolAddress((void**)&h_p,      g_h);
    cudaGetSymbolAddress((void**)&ah_p,     g_ah);
    cudaGetSymbolAddress((void**)&g_p,      g_pool);
    cudaGetSymbolAddress((void**)&cnt_p,    g_cnt);

    const int SMEM = 2 * 128 * APAD * (int)sizeof(__half);
    cudaFuncSetAttribute(hgemm128<true>,  cudaFuncAttributeMaxDynamicSharedMemorySize, SMEM);
    cudaFuncSetAttribute(hgemm128<false>, cudaFuncAttributeMaxDynamicSharedMemorySize, SMEM);

    // ---- CSR build + normalization ----
    cudaMemsetAsync(degi_p, 0, N * sizeof(int));
    hist_kernel<<<(E + 255) / 256, 256>>>(dst, degi_p, E);
    scan_kernel<<<1, 1024>>>(degi_p, rowptr_p, N);
    cudaMemcpyAsync(cursor_p, rowptr_p, N * sizeof(int), cudaMemcpyDeviceToDevice);
    fill_kernel<<<(E + 255) / 256, 256>>>(src, dst, cursor_p, csr_p, E);
    dinv_kernel<<<(N + 255) / 256, 256>>>(degi_p, dinv_p, N);

    const int gemmGrid = (N + 127) / 128;
    const int aggGrid  = (N * 32 + 255) / 256;

    // ---- layer 1 ----
    hgemm128<true><<<gemmGrid, 256, SMEM>>>(x, W1, dinv_p, h_p, N);
    agg_kernel<<<aggGrid, 256>>>(h_p, csr_p, rowptr_p, dinv_p, b1, ah_p, N);

    // ---- layer 2 ----
    hgemm128<false><<<gemmGrid, 256, SMEM>>>(ah_p, W2, dinv_p, h_p, N);
    agg_kernel<<<aggGrid, 256>>>(h_p, csr_p, rowptr_p, dinv_p, b2, ah_p, N);

    // ---- pooling + MLP ----
    cudaMemsetAsync(g_p, 0, NG * HID * sizeof(float));
    cudaMemsetAsync(cnt_p, 0, NG * sizeof(float));
    pool_kernel<<<(N + POOL_ROWS - 1) / POOL_ROWS, HID>>>(ah_p, batc, g_p, cnt_p, N);
    mlp_kernel<<<NG, HID>>>(g_p, cnt_p, Wc1, bc1, Wc2, bc2, (float*)d_out);
}